// round 1
// baseline (speedup 1.0000x reference)
#include <cuda_runtime.h>
#include <math.h>

// Problem constants
#define TT 2048
#define BB 4
#define II 1024
#define HH 1024
#define GG (4 * HH)  // 4096 gate rows

// ---------------- scratch (static device globals; no allocations) ----------
__device__ float g_pre[(size_t)TT * BB * GG];  // [8192][4096] precomputed x@W_in^T  (128 MB)
__device__ float g_h[2][BB * HH];              // double-buffered hidden state
__device__ unsigned g_bar;                     // global barrier counter (monotonic per launch)

// ---------------- init: reset barrier + h0 = 0 ------------------------------
__global__ void init_kernel() {
    int tid = blockIdx.x * blockDim.x + threadIdx.x;
    if (tid == 0) g_bar = 0u;
    int n = 2 * BB * HH;
    for (int i = tid; i < n; i += gridDim.x * blockDim.x) ((float*)g_h)[i] = 0.0f;
}

// ---------------- kernel 1: pre = x @ W_in^T  (M=8192, N=4096, K=1024) ------
// Both operands K-contiguous (NT layout). Tiled fp32: BM=128, BN=64, BK=16,
// 256 threads, 8x4 register tile per thread.
#define GBM 128
#define GBN 64
#define GBK 16

__global__ __launch_bounds__(256) void gemm_pre(const float* __restrict__ x,
                                                const float* __restrict__ Win) {
    __shared__ float As[GBK][GBM];
    __shared__ float Bs[GBK][GBN];
    const int tid = threadIdx.x;
    const int tx = tid & 15;        // 0..15  -> N
    const int ty = tid >> 4;        // 0..15  -> M
    const int mBase = blockIdx.y * GBM;
    const int nBase = blockIdx.x * GBN;

    float acc[8][4];
#pragma unroll
    for (int i = 0; i < 8; i++)
#pragma unroll
        for (int j = 0; j < 4; j++) acc[i][j] = 0.0f;

    for (int k0 = 0; k0 < II; k0 += GBK) {
        // Load A tile: 128 rows x 16 k = 512 float4
#pragma unroll
        for (int q = 0; q < 2; q++) {
            int id = tid * 2 + q;               // 0..511
            int m = id >> 2;
            int k4 = (id & 3) * 4;
            float4 v = *(const float4*)&x[(size_t)(mBase + m) * II + k0 + k4];
            As[k4 + 0][m] = v.x;
            As[k4 + 1][m] = v.y;
            As[k4 + 2][m] = v.z;
            As[k4 + 3][m] = v.w;
        }
        // Load B tile: 64 rows x 16 k = 256 float4
        {
            int id = tid;                        // 0..255
            int n = id >> 2;
            int k4 = (id & 3) * 4;
            float4 v = *(const float4*)&Win[(size_t)(nBase + n) * II + k0 + k4];
            Bs[k4 + 0][n] = v.x;
            Bs[k4 + 1][n] = v.y;
            Bs[k4 + 2][n] = v.z;
            Bs[k4 + 3][n] = v.w;
        }
        __syncthreads();

#pragma unroll
        for (int kk = 0; kk < GBK; kk++) {
            float a[8], b[4];
            *(float4*)&a[0] = *(const float4*)&As[kk][ty * 8];
            *(float4*)&a[4] = *(const float4*)&As[kk][ty * 8 + 4];
            *(float4*)&b[0] = *(const float4*)&Bs[kk][tx * 4];
#pragma unroll
            for (int i = 0; i < 8; i++)
#pragma unroll
                for (int j = 0; j < 4; j++) acc[i][j] = fmaf(a[i], b[j], acc[i][j]);
        }
        __syncthreads();
    }

#pragma unroll
    for (int i = 0; i < 8; i++) {
        float4 v = make_float4(acc[i][0], acc[i][1], acc[i][2], acc[i][3]);
        *(float4*)&g_pre[(size_t)(mBase + ty * 8 + i) * GG + nBase + tx * 4] = v;
    }
}

// ---------------- kernel 2: persistent recurrence ---------------------------
// 128 CTAs (all resident; 148 KB smem forces 1 CTA/SM). CTA k owns hidden units
// [8k, 8k+8): all 4 gate rows of W_hh for those units live in smem (128 KB).
// Each step: stage h (16 KB) to smem, 8 warps each compute 4 gate rows x 4
// batches over full K=1024, shuffle-reduce, 32 threads do the cell update, then
// a grid-wide spin barrier. h is double-buffered in global.
#define NBLK 128
#define UPB 8               // hidden units per block
#define ROWS (4 * UPB)      // 32 gate rows per block
#define RTH 256

__global__ __launch_bounds__(RTH) void lstm_rec(const float* __restrict__ Whh,
                                                float* __restrict__ out) {
    extern __shared__ float sm[];
    float* W_s = sm;                         // [32][1024]  128 KB
    float* h_s = W_s + ROWS * HH;            // [4][1024]    16 KB
    float* gates_s = h_s + BB * HH;          // [32 rows][4 batches] 512 B
    float* c_s = gates_s + ROWS * BB;        // [8 units][4 batches] 128 B

    const int tid = threadIdx.x;
    const int blk = blockIdx.x;
    const int warp = tid >> 5;
    const int lane = tid & 31;
    const int r0 = warp * 4;  // this warp's 4 gate rows

    // Stage this block's W_hh rows: row r = gate*8 + ulocal
    for (int id = tid; id < ROWS * (HH / 4); id += RTH) {
        int r = id / (HH / 4);
        int c4 = id % (HH / 4);
        int gate = r >> 3, ul = r & 7;
        ((float4*)&W_s[r * HH])[c4] =
            ((const float4*)&Whh[(size_t)(gate * HH + blk * UPB + ul) * HH])[c4];
    }
    if (tid < ROWS) c_s[tid] = 0.0f;  // 32 = units*batches

    for (int t = 0; t < TT; t++) {
        // Stage h_{t} (buffer t&1) into smem; __ldcg bypasses stale L1.
        const float4* hsrc = (const float4*)g_h[t & 1];
        for (int i = tid; i < (BB * HH) / 4; i += RTH)
            ((float4*)h_s)[i] = __ldcg(&hsrc[i]);
        __syncthreads();

        // Each warp: 4 rows x 4 batches over K=1024 (lane covers 4 consecutive
        // floats per iteration; iterations stride 128 -> conflict-free LDS.128).
        float acc[4][4];
#pragma unroll
        for (int j = 0; j < 4; j++)
#pragma unroll
            for (int b = 0; b < 4; b++) acc[j][b] = 0.0f;

#pragma unroll
        for (int it = 0; it < 8; it++) {
            const int base = it * 128 + lane * 4;
            float4 hv[4];
#pragma unroll
            for (int b = 0; b < 4; b++) hv[b] = *(const float4*)&h_s[b * HH + base];
#pragma unroll
            for (int j = 0; j < 4; j++) {
                float4 wv = *(const float4*)&W_s[(r0 + j) * HH + base];
#pragma unroll
                for (int b = 0; b < 4; b++) {
                    acc[j][b] = fmaf(wv.x, hv[b].x, acc[j][b]);
                    acc[j][b] = fmaf(wv.y, hv[b].y, acc[j][b]);
                    acc[j][b] = fmaf(wv.z, hv[b].z, acc[j][b]);
                    acc[j][b] = fmaf(wv.w, hv[b].w, acc[j][b]);
                }
            }
        }
        // Warp reduce 16 partials; lane 0 publishes to smem.
#pragma unroll
        for (int j = 0; j < 4; j++)
#pragma unroll
            for (int b = 0; b < 4; b++) {
                float v = acc[j][b];
                v += __shfl_xor_sync(0xFFFFFFFFu, v, 16);
                v += __shfl_xor_sync(0xFFFFFFFFu, v, 8);
                v += __shfl_xor_sync(0xFFFFFFFFu, v, 4);
                v += __shfl_xor_sync(0xFFFFFFFFu, v, 2);
                v += __shfl_xor_sync(0xFFFFFFFFu, v, 1);
                if (lane == 0) gates_s[(r0 + j) * 4 + b] = v;
            }
        __syncthreads();

        // Cell update: 32 threads = 8 units x 4 batches.
        if (tid < 32) {
            const int b = tid & 3;
            const int u = tid >> 2;
            const int ug = blk * UPB + u;
            const float* pre = &g_pre[(size_t)(t * BB + b) * GG + ug];
            float gi = pre[0 * HH] + gates_s[(0 * 8 + u) * 4 + b];
            float gf = pre[1 * HH] + gates_s[(1 * 8 + u) * 4 + b];
            float gc = pre[2 * HH] + gates_s[(2 * 8 + u) * 4 + b];
            float go = pre[3 * HH] + gates_s[(3 * 8 + u) * 4 + b];
            float i_s = 1.0f / (1.0f + expf(-gi));
            float f_s = 1.0f / (1.0f + expf(-gf));
            float g_t = tanhf(gc);
            float o_s = 1.0f / (1.0f + expf(-go));
            float c = f_s * c_s[tid] + i_s * g_t;
            c_s[tid] = c;
            float h = o_s * tanhf(c);
            g_h[(t + 1) & 1][b * HH + ug] = h;                      // next step's input
            out[(size_t)(t * BB + b) * HH + ug] = h;                // layer output
            if (t == TT - 1) {
                out[(size_t)TT * BB * HH + b * HH + ug] = h;            // h_T
                out[(size_t)TT * BB * HH + BB * HH + b * HH + ug] = c;  // c_T
            }
            __threadfence();  // publish h before the barrier arrive
        }
        __syncthreads();

        // Grid-wide barrier (monotonic counter; reset each launch by init_kernel).
        if (tid == 0) {
            atomicAdd(&g_bar, 1u);
            const unsigned target = (unsigned)(t + 1) * NBLK;
            while (*((volatile unsigned*)&g_bar) < target) {
            }
        }
        __syncthreads();
    }
}

// ---------------- launch ----------------------------------------------------
extern "C" void kernel_launch(void* const* d_in, const int* in_sizes, int n_in,
                              void* d_out, int out_size) {
    const float* x   = (const float*)d_in[0];   // [T,B,I]
    const float* Win = (const float*)d_in[1];   // [4H,I]
    const float* Whh = (const float*)d_in[2];   // [4H,H]
    float* out = (float*)d_out;

    const int smem_bytes = (ROWS * HH + BB * HH + ROWS * BB + ROWS) * (int)sizeof(float);
    cudaFuncSetAttribute(lstm_rec, cudaFuncAttributeMaxDynamicSharedMemorySize, smem_bytes);

    init_kernel<<<8, 256>>>();
    gemm_pre<<<dim3(GG / GBN, (TT * BB) / GBM), 256>>>(x, Win);
    lstm_rec<<<NBLK, RTH, smem_bytes>>>(Whh, out);
}

// round 4
// speedup vs baseline: 1.1499x; 1.1499x over previous
#include <cuda_runtime.h>
#include <math.h>

// Problem constants
#define TT 2048
#define BB 4
#define II 1024
#define HH 1024
#define GG (4 * HH)  // 4096 gate rows

// ---------------- scratch (static device globals; no allocations) ----------
__device__ float g_pre[(size_t)TT * BB * GG];  // [8192][4096] x@W_in^T (128 MB)
__device__ float g_h[2][BB * HH];              // double-buffered hidden state
__device__ unsigned g_bar;                     // global barrier counter (PROVEN in R1)

// packed fp32x2 FMA: d.lo += a.lo*b.lo ; d.hi += a.hi*b.hi (sm_100+)
__device__ __forceinline__ void ffma2(unsigned long long& d, unsigned long long a,
                                      unsigned long long b) {
    asm("fma.rn.f32x2 %0, %1, %2, %0;" : "+l"(d) : "l"(a), "l"(b));
}
__device__ __forceinline__ float ull_lo(unsigned long long v) {
    return __uint_as_float((unsigned)v);
}
__device__ __forceinline__ float ull_hi(unsigned long long v) {
    return __uint_as_float((unsigned)(v >> 32));
}

// ---------------- init: reset barrier + h0 = 0 ------------------------------
__global__ void init_kernel() {
    int tid = blockIdx.x * blockDim.x + threadIdx.x;
    if (tid == 0) g_bar = 0u;
    int n = 2 * BB * HH;
    for (int i = tid; i < n; i += gridDim.x * blockDim.x) ((float*)g_h)[i] = 0.0f;
}

// ---------------- kernel 1: pre = x @ W_in^T  (M=8192, N=4096, K=1024) ------
// fp32x2-packed tiled GEMM: BM=128, BN=64, BK=16, 256 threads, 8x4 tile/thread
// (accumulators packed along M: 4x4 ull = 16 FFMA2 per kk per thread).
#define GBM 128
#define GBN 64
#define GBK 16

__global__ __launch_bounds__(256) void gemm_pre(const float* __restrict__ x,
                                                const float* __restrict__ Win) {
    __shared__ __align__(16) float As[GBK][GBM];
    __shared__ __align__(16) float Bs[GBK][GBN];
    const int tid = threadIdx.x;
    const int tx = tid & 15;        // 0..15  -> N
    const int ty = tid >> 4;        // 0..15  -> M
    const int mBase = blockIdx.y * GBM;
    const int nBase = blockIdx.x * GBN;

    unsigned long long acc2[4][4];
#pragma unroll
    for (int i = 0; i < 4; i++)
#pragma unroll
        for (int j = 0; j < 4; j++) acc2[i][j] = 0ull;

    for (int k0 = 0; k0 < II; k0 += GBK) {
#pragma unroll
        for (int q = 0; q < 2; q++) {
            int id = tid * 2 + q;               // 0..511
            int m = id >> 2;
            int k4 = (id & 3) * 4;
            float4 v = *(const float4*)&x[(size_t)(mBase + m) * II + k0 + k4];
            As[k4 + 0][m] = v.x;
            As[k4 + 1][m] = v.y;
            As[k4 + 2][m] = v.z;
            As[k4 + 3][m] = v.w;
        }
        {
            int id = tid;                        // 0..255
            int n = id >> 2;
            int k4 = (id & 3) * 4;
            float4 v = *(const float4*)&Win[(size_t)(nBase + n) * II + k0 + k4];
            Bs[k4 + 0][n] = v.x;
            Bs[k4 + 1][n] = v.y;
            Bs[k4 + 2][n] = v.z;
            Bs[k4 + 3][n] = v.w;
        }
        __syncthreads();

#pragma unroll
        for (int kk = 0; kk < GBK; kk++) {
            ulonglong2 t0 = *(const ulonglong2*)&As[kk][ty * 8];
            ulonglong2 t1 = *(const ulonglong2*)&As[kk][ty * 8 + 4];
            unsigned long long a2[4] = {t0.x, t0.y, t1.x, t1.y};
            float bq[4];
            *(float4*)&bq[0] = *(const float4*)&Bs[kk][tx * 4];
            unsigned long long bd[4];
#pragma unroll
            for (int j = 0; j < 4; j++) {
                unsigned bu = __float_as_uint(bq[j]);
                asm("mov.b64 %0, {%1, %1};" : "=l"(bd[j]) : "r"(bu));
            }
#pragma unroll
            for (int i = 0; i < 4; i++)
#pragma unroll
                for (int j = 0; j < 4; j++) ffma2(acc2[i][j], a2[i], bd[j]);
        }
        __syncthreads();
    }

#pragma unroll
    for (int i = 0; i < 4; i++) {
        float4 vlo = make_float4(ull_lo(acc2[i][0]), ull_lo(acc2[i][1]),
                                 ull_lo(acc2[i][2]), ull_lo(acc2[i][3]));
        float4 vhi = make_float4(ull_hi(acc2[i][0]), ull_hi(acc2[i][1]),
                                 ull_hi(acc2[i][2]), ull_hi(acc2[i][3]));
        *(float4*)&g_pre[(size_t)(mBase + ty * 8 + 2 * i + 0) * GG + nBase + tx * 4] = vlo;
        *(float4*)&g_pre[(size_t)(mBase + ty * 8 + 2 * i + 1) * GG + nBase + tx * 4] = vhi;
    }
}

// ---------------- kernel 2: persistent recurrence ---------------------------
// 128 CTAs x 256 threads (8 warps). CTA owns 8 hidden units (32 gate rows in
// smem, 128 KB). Warp w: gate = w>>1, K-half = w&1; computes 8 rows x 4 batches
// over K=512 with packed FFMA2, then a register transpose-reduce (31 shfl).
// Partials for the two K-halves are summed by warp 0 in the cell update
// (c-state lives in warp-0 registers). Grid sync = R1-PROVEN atomic barrier
// with nanosleep backoff.
#define NBLK 128
#define UPB 8
#define ROWS 32
#define RTH 256

__global__ __launch_bounds__(RTH) void lstm_rec(const float* __restrict__ Whh,
                                                float* __restrict__ out) {
    extern __shared__ float sm[];
    float* W_s = sm;                          // [32][1024] 128 KB
    float* h_s = W_s + ROWS * HH;             // [4][1024]   16 KB
    float* part_s = h_s + BB * HH;            // [2 khalf][4 gate][32]  1 KB

    const int tid = threadIdx.x;
    const int blk = blockIdx.x;
    const int warp = tid >> 5;
    const int lane = tid & 31;
    const int gate = warp >> 1;               // 0..3
    const int khalf = warp & 1;               // 0..1

    // Stage W: local row r = gate*8 + u  <-  Whh[gate*1024 + blk*8 + u]
    for (int id = tid; id < ROWS * (HH / 4); id += RTH) {
        int r = id / (HH / 4);
        int c4 = id % (HH / 4);
        int g = r >> 3, ul = r & 7;
        ((float4*)&W_s[r * HH])[c4] =
            ((const float4*)&Whh[(size_t)(g * HH + blk * UPB + ul) * HH])[c4];
    }
    __syncthreads();

    // warp0 persistent cell state: lane = u*4 + b
    const int u = lane >> 2, b = lane & 3;
    const int ug = blk * UPB + u;
    float c_val = 0.0f;

    const float* Wbase = &W_s[gate * UPB * HH + khalf * (HH / 2)];
    const float* hbase = &h_s[khalf * (HH / 2)];

    for (int t = 0; t < TT; t++) {
        // Prefetch this step's pre-activations (consumed ~2000 cyc later).
        float pre_r[4];
        if (warp == 0) {
#pragma unroll
            for (int g = 0; g < 4; g++)
                pre_r[g] = __ldcs(&g_pre[(size_t)(t * BB + b) * GG + g * HH + ug]);
        }

        // Stage h_t (buffer t&1) into smem; __ldcg bypasses stale L1.
        const float4* hsrc = (const float4*)g_h[t & 1];
        for (int i = tid; i < (BB * HH) / 4; i += RTH)
            ((float4*)h_s)[i] = __ldcg(&hsrc[i]);
        __syncthreads();

        // GEMV: 8 rows x 4 batches over K=512 (4 iterations of 128).
        unsigned long long acc[8][4];
#pragma unroll
        for (int j = 0; j < 8; j++)
#pragma unroll
            for (int bb = 0; bb < 4; bb++) acc[j][bb] = 0ull;

#pragma unroll
        for (int it = 0; it < 4; it++) {
            const int base = it * 128 + lane * 4;
            ulonglong2 hv[4];
#pragma unroll
            for (int bb = 0; bb < 4; bb++)
                hv[bb] = *(const ulonglong2*)&hbase[bb * HH + base];
#pragma unroll
            for (int j = 0; j < 8; j++) {
                ulonglong2 wv = *(const ulonglong2*)&Wbase[j * HH + base];
#pragma unroll
                for (int bb = 0; bb < 4; bb++) {
                    ffma2(acc[j][bb], wv.x, hv[bb].x);
                    ffma2(acc[j][bb], wv.y, hv[bb].y);
                }
            }
        }

        // Collapse packed accumulators -> 32 scalars (index = j*4 + bb = u*4+b)
        float a[32];
#pragma unroll
        for (int j = 0; j < 8; j++)
#pragma unroll
            for (int bb = 0; bb < 4; bb++)
                a[j * 4 + bb] = ull_lo(acc[j][bb]) + ull_hi(acc[j][bb]);

        // Register transpose-reduce: lane l ends with full sum of index l.
#pragma unroll
        for (int s = 16; s >= 1; s >>= 1) {
            const bool up = (lane & s) != 0;
#pragma unroll
            for (int k = 0; k < s; k++) {
                float sendv = up ? a[k] : a[k + s];
                float keepv = up ? a[k + s] : a[k];
                float got = __shfl_xor_sync(0xFFFFFFFFu, sendv, s);
                a[k] = keepv + got;
            }
        }
        part_s[(khalf * 4 + gate) * 32 + lane] = a[0];
        __syncthreads();

        // Cell update: warp 0, lane = u*4 + b. Sum the two K-half partials.
        if (tid < 32) {
            float gi = pre_r[0] + part_s[0 * 32 + lane] + part_s[4 * 32 + lane];
            float gf = pre_r[1] + part_s[1 * 32 + lane] + part_s[5 * 32 + lane];
            float gc = pre_r[2] + part_s[2 * 32 + lane] + part_s[6 * 32 + lane];
            float go = pre_r[3] + part_s[3 * 32 + lane] + part_s[7 * 32 + lane];
            float i_s = 1.0f / (1.0f + __expf(-gi));
            float f_s = 1.0f / (1.0f + __expf(-gf));
            float o_s = 1.0f / (1.0f + __expf(-go));
            float g_t = tanhf(gc);
            c_val = f_s * c_val + i_s * g_t;
            float h = o_s * tanhf(c_val);
            g_h[(t + 1) & 1][b * HH + ug] = h;                      // next step input
            out[(size_t)(t * BB + b) * HH + ug] = h;                // layer output
            if (t == TT - 1) {
                out[(size_t)TT * BB * HH + b * HH + ug] = h;            // h_T
                out[(size_t)TT * BB * HH + BB * HH + b * HH + ug] = c_val;  // c_T
            }
            __threadfence();  // all 32 writers fence their h stores before arrive
        }
        __syncthreads();

        // Grid-wide barrier: R1-proven atomic counter + volatile poll,
        // with nanosleep backoff to cut L2 poll pressure.
        if (tid == 0) {
            atomicAdd(&g_bar, 1u);
            const unsigned target = (unsigned)(t + 1) * NBLK;
            while (*((volatile unsigned*)&g_bar) < target) __nanosleep(64);
        }
        __syncthreads();
    }
}

// ---------------- launch ----------------------------------------------------
extern "C" void kernel_launch(void* const* d_in, const int* in_sizes, int n_in,
                              void* d_out, int out_size) {
    const float* x   = (const float*)d_in[0];   // [T,B,I]
    const float* Win = (const float*)d_in[1];   // [4H,I]
    const float* Whh = (const float*)d_in[2];   // [4H,H]
    float* out = (float*)d_out;

    const int smem_bytes = (ROWS * HH + BB * HH + 2 * 4 * 32) * (int)sizeof(float);
    cudaFuncSetAttribute(lstm_rec, cudaFuncAttributeMaxDynamicSharedMemorySize, smem_bytes);

    init_kernel<<<8, 256>>>();
    gemm_pre<<<dim3(GG / GBN, (TT * BB) / GBM), 256>>>(x, Win);
    lstm_rec<<<NBLK, RTH, smem_bytes>>>(Whh, out);
}